// round 13
// baseline (speedup 1.0000x reference)
#include <cuda_runtime.h>
#include <cuda_bf16.h>
#include <math.h>
#include <stdint.h>

#define BB 32
#define TT 1024
#define HH 1024
#define W2 2048

// ---------------------------------------------------------------------------
// Device scratch (no cudaMalloc allowed)
// ---------------------------------------------------------------------------
__device__ float g_q[BB * HH];
__device__ int   g_qcnt[8][32];        // per-(gblock, batch) completion counter
__device__ float g_epart[8][BB][TT];   // partial energies per g-block
__device__ __align__(16) __nv_bfloat16 g_Bhi[HH * HH];
__device__ __align__(16) __nv_bfloat16 g_Blo[HH * HH];

// ---------------------------------------------------------------------------
// Helpers
// ---------------------------------------------------------------------------
__device__ __forceinline__ uint32_t smem_to_u32(const void* p) {
    uint32_t a;
    asm("{ .reg .u64 t; cvta.to.shared.u64 t, %1; cvt.u32.u64 %0, t; }" : "=r"(a) : "l"(p));
    return a;
}

#define CP_ASYNC_16(dst, src) \
    asm volatile("cp.async.cg.shared.global [%0], [%1], 16;" :: "r"((uint32_t)(dst)), "l"(src) : "memory")
#define CP_COMMIT() asm volatile("cp.async.commit_group;" ::: "memory")
#define CP_WAIT(n)  asm volatile("cp.async.wait_group %0;" :: "n"(n) : "memory")

#define LDSM4(r, addr) \
    asm volatile("ldmatrix.sync.aligned.m8n8.x4.shared.b16 {%0,%1,%2,%3}, [%4];" \
        : "=r"((r)[0]), "=r"((r)[1]), "=r"((r)[2]), "=r"((r)[3]) : "r"(addr))

#define MMA16816(d, a, b0, b1) \
    asm volatile("mma.sync.aligned.m16n8k16.row.col.f32.bf16.bf16.f32 " \
        "{%0,%1,%2,%3}, {%4,%5,%6,%7}, {%8,%9}, {%0,%1,%2,%3};" \
        : "+f"((d)[0]), "+f"((d)[1]), "+f"((d)[2]), "+f"((d)[3]) \
        : "r"((a)[0]), "r"((a)[1]), "r"((a)[2]), "r"((a)[3]), "r"(b0), "r"(b1))

// FMA-only reciprocal (q > 0): bit-hack seed + 3 Newton steps
__device__ __forceinline__ float rcp_fma(float q) {
    float y = __uint_as_float(0x7EF311C3u - __float_as_uint(q));
    y = y * fmaf(-q, y, 2.0f);
    y = y * fmaf(-q, y, 2.0f);
    y = y * fmaf(-q, y, 2.0f);
    return y;
}

// FMA-only tanh (XLA 13/6 rational minimax), abs err ~1e-7. NO MUFU.
__device__ __forceinline__ float fast_tanh(float x) {
    float xc = fminf(fmaxf(x, -7.90531f), 7.90531f);
    float x2 = xc * xc;
    float p = -2.76076847742355e-16f;
    p = fmaf(p, x2,  2.00018790482477e-13f);
    p = fmaf(p, x2, -8.60467152213735e-11f);
    p = fmaf(p, x2,  5.12229709037114e-08f);
    p = fmaf(p, x2,  1.48572235717979e-05f);
    p = fmaf(p, x2,  6.37261928875436e-04f);
    p = fmaf(p, x2,  4.89352455891786e-03f);
    p = p * xc;
    float q = 1.19825839466702e-06f;
    q = fmaf(q, x2, 1.18534705686654e-04f);
    q = fmaf(q, x2, 2.26843463243900e-03f);
    q = fmaf(q, x2, 4.89352518554385e-03f);
    return p * rcp_fma(q);
}

// Split 8 consecutive floats into bf16 hi / lo packs
__device__ __forceinline__ void split8(const float4& f0, const float4& f1,
                                       uint4& uh, uint4& ul) {
    float f[8] = {f0.x, f0.y, f0.z, f0.w, f1.x, f1.y, f1.z, f1.w};
    uint32_t h[8], l[8];
    #pragma unroll
    for (int j = 0; j < 8; j++) {
        __nv_bfloat16 hb = __float2bfloat16(f[j]);
        float r = f[j] - __bfloat162float(hb);
        h[j] = (uint32_t)__bfloat16_as_ushort(hb);
        l[j] = (uint32_t)__bfloat16_as_ushort(__float2bfloat16(r));
    }
    uh.x = h[0] | (h[1] << 16); uh.y = h[2] | (h[3] << 16);
    uh.z = h[4] | (h[5] << 16); uh.w = h[6] | (h[7] << 16);
    ul.x = l[0] | (l[1] << 16); ul.y = l[2] | (l[3] << 16);
    ul.z = l[4] | (l[5] << 16); ul.w = l[6] | (l[7] << 16);
}

// ---------------------------------------------------------------------------
// prep: convertB (We -> bf16 hi/lo) + zero the q counters.
// qproj itself is computed inside energy CTA prologues (hidden under GEMM).
// ---------------------------------------------------------------------------
__global__ void __launch_bounds__(256) prep_kernel(const float* __restrict__ W)
{
    if (blockIdx.x == 0)
        ((int*)g_qcnt)[threadIdx.x] = 0;    // 256 counters exactly

    size_t i8 = ((size_t)blockIdx.x * 256 + threadIdx.x) * 8;
    size_t g = i8 >> 10, h = i8 & 1023;
    const float* src = W + g * W2 + HH + h;
    float4 f0 = *(const float4*)src;
    float4 f1 = *(const float4*)(src + 4);
    uint4 uh, ul;
    split8(f0, f1, uh, ul);
    *(uint4*)&g_Bhi[i8] = uh;
    *(uint4*)&g_Blo[i8] = ul;
}

// ---------------------------------------------------------------------------
// Main kernel: split-bf16 mma.sync GEMM (BM=128 t, BN=128 g, BK=32).
// 256 threads = 8 warps (4x2), warp tile 32x64, 2 CTAs/SM.
// 3-stage cp.async pipeline, ONE __syncthreads per k-chunk (mainloop is the
// proven 652us R10 body, untouched).
// qproj distributed: each CTA of a (g-block, b) octet computes 16 rows of
// q[b, g0..g0+128) in its PROLOGUE; epilogue spins on an 8-count flag.
// grid = (8, 8, 32).
// ---------------------------------------------------------------------------
#define OFFA_HI 0
#define OFFA_LO 8192
#define OFFB_HI 16384
#define OFFB_LO 24576
#define LO_DELTA 8192
#define STAGE_BYTES 32768
#define SMEM_BYTES (3 * STAGE_BYTES)    // 98304 dynamic

__global__ void __launch_bounds__(256, 2) energy_kernel(
    const float* __restrict__ enc, const float* __restrict__ v,
    const float* __restrict__ W, const float* __restrict__ hidden,
    const float* __restrict__ bias)
{
    extern __shared__ char smem[];
    const uint32_t sb = smem_to_u32(smem);
    __shared__ float esm[128];

    const int tid = threadIdx.x;
    const int lane = tid & 31, wid = tid >> 5;
    const int warp_m = wid & 3, warp_n = wid >> 2;
    const int t0 = blockIdx.x * 128, g0 = blockIdx.y * 128, b = blockIdx.z;

    if (tid < 128) esm[tid] = 0.f;

    // Loader mapping: 2 threads per row; each covers 16 elems (cols half*16..)
    const int lrow = tid >> 1;
    const int half = tid & 1;
    const float* pA = enc + ((size_t)(b * TT + t0 + lrow)) * HH + half * 16;
    const __nv_bfloat16* pBh = g_Bhi + ((size_t)(g0 + lrow)) * HH + half * 16;
    const __nv_bfloat16* pBl = g_Blo + ((size_t)(g0 + lrow)) * HH + half * 16;
    // SW64 swizzled destination offsets (two 16B chunks per thread)
    const uint32_t xr_l = ((uint32_t)lrow >> 1) & 3;
    const uint32_t dstc0 = (uint32_t)lrow * 64 + (((uint32_t)(half * 2 + 0) ^ xr_l) * 16);
    const uint32_t dstc1 = (uint32_t)lrow * 64 + (((uint32_t)(half * 2 + 1) ^ xr_l) * 16);

    float acc[2][8][4];
    #pragma unroll
    for (int i = 0; i < 2; i++)
        #pragma unroll
        for (int j = 0; j < 8; j++)
            #pragma unroll
            for (int k = 0; k < 4; k++) acc[i][j][k] = 0.f;

    // Precomputed ldmatrix offsets (relative to stage base), SW64-swizzled.
    const uint32_t lr15 = (uint32_t)(lane & 15);
    const uint32_t ch   = (uint32_t)(lane >> 4);
    const uint32_t xr   = (lr15 >> 1) & 3;
    uint32_t aoff[2][2], boff[4][2];
    #pragma unroll
    for (int i = 0; i < 2; i++)
        #pragma unroll
        for (int s = 0; s < 2; s++)
            aoff[i][s] = OFFA_HI + (uint32_t)(warp_m * 32 + i * 16 + lr15) * 64
                       + ((((uint32_t)s * 2 + ch) ^ xr) * 16);
    #pragma unroll
    for (int i = 0; i < 4; i++)
        #pragma unroll
        for (int s = 0; s < 2; s++)
            boff[i][s] = OFFB_HI + (uint32_t)(warp_n * 64 + i * 16 + lr15) * 64
                       + ((((uint32_t)s * 2 + ch) ^ xr) * 16);

    #define ISSUE_B(stagebase, kc) do { \
        const int ko_ = (kc) * 32; \
        CP_ASYNC_16((stagebase) + OFFB_HI + dstc0, pBh + ko_); \
        CP_ASYNC_16((stagebase) + OFFB_HI + dstc1, pBh + ko_ + 8); \
        CP_ASYNC_16((stagebase) + OFFB_LO + dstc0, pBl + ko_); \
        CP_ASYNC_16((stagebase) + OFFB_LO + dstc1, pBl + ko_ + 8); \
    } while (0)

    #define STS_A(stageoff, f0, f1, f2, f3) do { \
        uint4 uh, ul; \
        split8(f0, f1, uh, ul); \
        *(uint4*)(smem + (stageoff) + OFFA_HI + dstc0) = uh; \
        *(uint4*)(smem + (stageoff) + OFFA_LO + dstc0) = ul; \
        split8(f2, f3, uh, ul); \
        *(uint4*)(smem + (stageoff) + OFFA_HI + dstc1) = uh; \
        *(uint4*)(smem + (stageoff) + OFFA_LO + dstc1) = ul; \
    } while (0)

    // ---- prologue: fill stages 0 and 1 ----
    #pragma unroll
    for (int st = 0; st < 2; st++) {
        const float* p = pA + st * 32;
        float4 a0 = *(const float4*)(p + 0);
        float4 a1 = *(const float4*)(p + 4);
        float4 a2 = *(const float4*)(p + 8);
        float4 a3 = *(const float4*)(p + 12);
        ISSUE_B(sb + st * STAGE_BYTES, st);
        CP_COMMIT();
        STS_A(st * STAGE_BYTES, a0, a1, a2, a3);
    }

    // ---- distributed qproj (outside the mainloop): 16 rows per CTA ----
    // 16 threads per row; row = tid>>4 (0..15); strip of 64 elems per thread.
    {
        const int qrow = tid >> 4;
        const int t16  = tid & 15;
        const int g    = g0 + blockIdx.x * 16 + qrow;
        const float* wr = W + (size_t)g * W2 + t16 * 64;
        const float* hr = hidden + (size_t)b * HH + t16 * 64;
        float s = 0.f;
        #pragma unroll
        for (int j = 0; j < 16; j++) {
            float4 wv = *(const float4*)(wr + j * 4);
            float4 hv = *(const float4*)(hr + j * 4);
            s = fmaf(wv.x, hv.x, s);
            s = fmaf(wv.y, hv.y, s);
            s = fmaf(wv.z, hv.z, s);
            s = fmaf(wv.w, hv.w, s);
        }
        #pragma unroll
        for (int off = 8; off; off >>= 1)
            s += __shfl_xor_sync(0xffffffffu, s, off);
        if (t16 == 0)
            g_q[b * HH + g] = s + bias[g];
        __threadfence();
        __syncthreads();
        if (tid == 0)
            atomicAdd(&g_qcnt[blockIdx.y][b], 1);
    }

    for (int kc = 0; kc < 32; kc++) {
        const int bufc = kc % 3;
        const int bufn = (kc + 2) % 3;

        float4 a0, a1, a2, a3;
        if (kc < 30) {
            const float* p = pA + (kc + 2) * 32;
            a0 = *(const float4*)(p + 0);
            a1 = *(const float4*)(p + 4);
            a2 = *(const float4*)(p + 8);
            a3 = *(const float4*)(p + 12);
        }

        if (kc == 31) { CP_WAIT(0); } else { CP_WAIT(1); }
        __syncthreads();

        if (kc < 30) {
            ISSUE_B(sb + bufn * STAGE_BYTES, kc + 2);
            CP_COMMIT();
        }

        const uint32_t st = sb + (uint32_t)bufc * STAGE_BYTES;

        // ---- s = 0 ----
        {
            uint32_t ah[2][4], al[2][4];
            #pragma unroll
            for (int mt = 0; mt < 2; mt++) {
                LDSM4(ah[mt], st + aoff[mt][0]);
                LDSM4(al[mt], st + aoff[mt][0] + LO_DELTA);
            }
            #pragma unroll
            for (int np = 0; np < 4; np++) {
                uint32_t bh[4], bl[4];
                LDSM4(bh, st + boff[np][0]);
                LDSM4(bl, st + boff[np][0] + LO_DELTA);
                float* a00 = acc[0][np * 2 + 0];
                float* a01 = acc[0][np * 2 + 1];
                float* a10 = acc[1][np * 2 + 0];
                float* a11 = acc[1][np * 2 + 1];
                MMA16816(a00, ah[0], bh[0], bh[2]);
                MMA16816(a10, ah[1], bh[0], bh[2]);
                MMA16816(a01, ah[0], bh[1], bh[3]);
                MMA16816(a11, ah[1], bh[1], bh[3]);
                MMA16816(a00, ah[0], bl[0], bl[2]);
                MMA16816(a10, ah[1], bl[0], bl[2]);
                MMA16816(a01, ah[0], bl[1], bl[3]);
                MMA16816(a11, ah[1], bl[1], bl[3]);
                MMA16816(a00, al[0], bh[0], bh[2]);
                MMA16816(a10, al[1], bh[0], bh[2]);
                MMA16816(a01, al[0], bh[1], bh[3]);
                MMA16816(a11, al[1], bh[1], bh[3]);
            }
        }

        // split + store A for stage kc+2 (buffer freed by this iter's sync)
        if (kc < 30)
            STS_A((uint32_t)bufn * STAGE_BYTES, a0, a1, a2, a3);

        // ---- s = 1 ----
        {
            uint32_t ah[2][4], al[2][4];
            #pragma unroll
            for (int mt = 0; mt < 2; mt++) {
                LDSM4(ah[mt], st + aoff[mt][1]);
                LDSM4(al[mt], st + aoff[mt][1] + LO_DELTA);
            }
            #pragma unroll
            for (int np = 0; np < 4; np++) {
                uint32_t bh[4], bl[4];
                LDSM4(bh, st + boff[np][1]);
                LDSM4(bl, st + boff[np][1] + LO_DELTA);
                float* a00 = acc[0][np * 2 + 0];
                float* a01 = acc[0][np * 2 + 1];
                float* a10 = acc[1][np * 2 + 0];
                float* a11 = acc[1][np * 2 + 1];
                MMA16816(a00, ah[0], bh[0], bh[2]);
                MMA16816(a10, ah[1], bh[0], bh[2]);
                MMA16816(a01, ah[0], bh[1], bh[3]);
                MMA16816(a11, ah[1], bh[1], bh[3]);
                MMA16816(a00, ah[0], bl[0], bl[2]);
                MMA16816(a10, ah[1], bl[0], bl[2]);
                MMA16816(a01, ah[0], bl[1], bl[3]);
                MMA16816(a11, ah[1], bl[1], bl[3]);
                MMA16816(a00, al[0], bh[0], bh[2]);
                MMA16816(a10, al[1], bh[0], bh[2]);
                MMA16816(a01, al[0], bh[1], bh[3]);
                MMA16816(a11, al[1], bh[1], bh[3]);
            }
        }
    }

    // Wait for the full q slice (all 8 octet CTAs arrived ~600us ago)
    if (tid == 0) {
        while (atomicAdd(&g_qcnt[blockIdx.y][b], 0) < 8) {}
    }
    __syncthreads();

    // ---- epilogue: tanh(acc + q) * v, reduce per t-row ----
    const float* qrow = g_q + b * HH + g0 + warp_n * 64;
    const float* vrow = v + g0 + warp_n * 64;
    float part[2][2] = {{0.f, 0.f}, {0.f, 0.f}};
    #pragma unroll
    for (int np = 0; np < 4; np++) {
        #pragma unroll
        for (int nt = 0; nt < 2; nt++) {
            const int gl = np * 16 + nt * 8 + (lane & 3) * 2;
            const float2 q2 = *(const float2*)(qrow + gl);
            const float2 v2 = *(const float2*)(vrow + gl);
            #pragma unroll
            for (int mt = 0; mt < 2; mt++) {
                const float* c = acc[mt][np * 2 + nt];
                #pragma unroll
                for (int rh = 0; rh < 2; rh++) {
                    part[mt][rh] += fast_tanh(c[rh * 2 + 0] + q2.x) * v2.x
                                  + fast_tanh(c[rh * 2 + 1] + q2.y) * v2.y;
                }
            }
        }
    }
    #pragma unroll
    for (int mt = 0; mt < 2; mt++) {
        #pragma unroll
        for (int rh = 0; rh < 2; rh++) {
            float p = part[mt][rh];
            p += __shfl_xor_sync(0xffffffffu, p, 1);
            p += __shfl_xor_sync(0xffffffffu, p, 2);
            if ((lane & 3) == 0)
                atomicAdd(&esm[warp_m * 32 + mt * 16 + rh * 8 + (lane >> 2)], p);
        }
    }
    __syncthreads();
    if (tid < 128)
        g_epart[blockIdx.y][b][t0 + tid] = esm[tid];
}

// ---------------------------------------------------------------------------
// Softmax over t: 1024 threads, one element per thread.
// ---------------------------------------------------------------------------
__global__ void __launch_bounds__(1024) softmax_kernel(float* __restrict__ out)
{
    const int b = blockIdx.x;
    const int tid = threadIdx.x;
    const int lane = tid & 31, wid = tid >> 5;
    __shared__ float red[32];
    __shared__ float bc;

    float e = 0.f;
    #pragma unroll
    for (int sl = 0; sl < 8; sl++) e += g_epart[sl][b][tid];

    float m = e;
    #pragma unroll
    for (int off = 16; off; off >>= 1) m = fmaxf(m, __shfl_xor_sync(0xffffffffu, m, off));
    if (lane == 0) red[wid] = m;
    __syncthreads();
    if (tid < 32) {
        float mm = red[tid];
        #pragma unroll
        for (int off = 16; off; off >>= 1) mm = fmaxf(mm, __shfl_xor_sync(0xffffffffu, mm, off));
        if (tid == 0) bc = mm;
    }
    __syncthreads();
    const float M = bc;

    float ex = expf(e - M);
    float s = ex;
    #pragma unroll
    for (int off = 16; off; off >>= 1) s += __shfl_xor_sync(0xffffffffu, s, off);
    if (lane == 0) red[wid] = s;
    __syncthreads();
    if (tid < 32) {
        float ss = red[tid];
        #pragma unroll
        for (int off = 16; off; off >>= 1) ss += __shfl_xor_sync(0xffffffffu, ss, off);
        if (tid == 0) bc = 1.0f / ss;
    }
    __syncthreads();

    out[(size_t)b * TT + tid] = ex * bc;
}

// ---------------------------------------------------------------------------
extern "C" void kernel_launch(void* const* d_in, const int* in_sizes, int n_in,
                              void* d_out, int out_size)
{
    const float* hidden = (const float*)d_in[0];  // (1, 32, 1024)
    const float* enc    = (const float*)d_in[1];  // (32, 1024, 1024)
    const float* W      = (const float*)d_in[2];  // (1024, 2048)
    const float* bias   = (const float*)d_in[3];  // (1024,)
    const float* v      = (const float*)d_in[4];  // (1024,)
    float* out = (float*)d_out;                   // (32, 1, 1024)

    cudaFuncSetAttribute(energy_kernel,
                         cudaFuncAttributeMaxDynamicSharedMemorySize, SMEM_BYTES);

    prep_kernel<<<512, 256>>>(W);
    energy_kernel<<<dim3(TT / 128, HH / 128, BB), 256, SMEM_BYTES>>>(enc, v, W, hidden, bias);
    softmax_kernel<<<BB, 1024>>>(out);
}

// round 14
// speedup vs baseline: 1.8763x; 1.8763x over previous
#include <cuda_runtime.h>
#include <cuda_bf16.h>
#include <math.h>
#include <stdint.h>

#define BB 32
#define TT 1024
#define HH 1024
#define W2 2048

// ---------------------------------------------------------------------------
// Device scratch (no cudaMalloc allowed)
// ---------------------------------------------------------------------------
__device__ float g_q[BB * HH];
__device__ float g_epart[8][BB][TT];   // partial energies per g-block
__device__ __align__(16) __nv_bfloat16 g_Bhi[HH * HH];
__device__ __align__(16) __nv_bfloat16 g_Blo[HH * HH];

// ---------------------------------------------------------------------------
// Helpers
// ---------------------------------------------------------------------------
__device__ __forceinline__ uint32_t smem_to_u32(const void* p) {
    uint32_t a;
    asm("{ .reg .u64 t; cvta.to.shared.u64 t, %1; cvt.u32.u64 %0, t; }" : "=r"(a) : "l"(p));
    return a;
}

#define CP_ASYNC_16(dst, src) \
    asm volatile("cp.async.cg.shared.global [%0], [%1], 16;" :: "r"((uint32_t)(dst)), "l"(src) : "memory")
#define CP_COMMIT() asm volatile("cp.async.commit_group;" ::: "memory")
#define CP_WAIT(n)  asm volatile("cp.async.wait_group %0;" :: "n"(n) : "memory")

#define LDSM4(r, addr) \
    asm volatile("ldmatrix.sync.aligned.m8n8.x4.shared.b16 {%0,%1,%2,%3}, [%4];" \
        : "=r"((r)[0]), "=r"((r)[1]), "=r"((r)[2]), "=r"((r)[3]) : "r"(addr))

#define MMA16816(d, a, b0, b1) \
    asm volatile("mma.sync.aligned.m16n8k16.row.col.f32.bf16.bf16.f32 " \
        "{%0,%1,%2,%3}, {%4,%5,%6,%7}, {%8,%9}, {%0,%1,%2,%3};" \
        : "+f"((d)[0]), "+f"((d)[1]), "+f"((d)[2]), "+f"((d)[3]) \
        : "r"((a)[0]), "r"((a)[1]), "r"((a)[2]), "r"((a)[3]), "r"(b0), "r"(b1))

// FMA-only reciprocal (q > 0): bit-hack seed + 3 Newton steps
__device__ __forceinline__ float rcp_fma(float q) {
    float y = __uint_as_float(0x7EF311C3u - __float_as_uint(q));
    y = y * fmaf(-q, y, 2.0f);
    y = y * fmaf(-q, y, 2.0f);
    y = y * fmaf(-q, y, 2.0f);
    return y;
}

// FMA-only tanh (XLA 13/6 rational minimax), abs err ~1e-7. NO MUFU.
__device__ __forceinline__ float fast_tanh(float x) {
    float xc = fminf(fmaxf(x, -7.90531f), 7.90531f);
    float x2 = xc * xc;
    float p = -2.76076847742355e-16f;
    p = fmaf(p, x2,  2.00018790482477e-13f);
    p = fmaf(p, x2, -8.60467152213735e-11f);
    p = fmaf(p, x2,  5.12229709037114e-08f);
    p = fmaf(p, x2,  1.48572235717979e-05f);
    p = fmaf(p, x2,  6.37261928875436e-04f);
    p = fmaf(p, x2,  4.89352455891786e-03f);
    p = p * xc;
    float q = 1.19825839466702e-06f;
    q = fmaf(q, x2, 1.18534705686654e-04f);
    q = fmaf(q, x2, 2.26843463243900e-03f);
    q = fmaf(q, x2, 4.89352518554385e-03f);
    return p * rcp_fma(q);
}

// Split 8 consecutive floats into bf16 hi / lo packs
__device__ __forceinline__ void split8(const float4& f0, const float4& f1,
                                       uint4& uh, uint4& ul) {
    float f[8] = {f0.x, f0.y, f0.z, f0.w, f1.x, f1.y, f1.z, f1.w};
    uint32_t h[8], l[8];
    #pragma unroll
    for (int j = 0; j < 8; j++) {
        __nv_bfloat16 hb = __float2bfloat16(f[j]);
        float r = f[j] - __bfloat162float(hb);
        h[j] = (uint32_t)__bfloat16_as_ushort(hb);
        l[j] = (uint32_t)__bfloat16_as_ushort(__float2bfloat16(r));
    }
    uh.x = h[0] | (h[1] << 16); uh.y = h[2] | (h[3] << 16);
    uh.z = h[4] | (h[5] << 16); uh.w = h[6] | (h[7] << 16);
    ul.x = l[0] | (l[1] << 16); ul.y = l[2] | (l[3] << 16);
    ul.z = l[4] | (l[5] << 16); ul.w = l[6] | (l[7] << 16);
}

// ---------------------------------------------------------------------------
// prep: blocks [0,512) convertB; blocks [512, 512+4096) qproj, one block per
// (g-block, b) pair -> fully parallel, no serial batch loop. (R10 exact)
// ---------------------------------------------------------------------------
__global__ void __launch_bounds__(256) prep_kernel(
    const float* __restrict__ W, const float* __restrict__ hidden,
    const float* __restrict__ bias)
{
    if (blockIdx.x < 512) {
        size_t i8 = ((size_t)blockIdx.x * 256 + threadIdx.x) * 8;
        size_t g = i8 >> 10, h = i8 & 1023;
        const float* src = W + g * W2 + HH + h;
        float4 f0 = *(const float4*)src;
        float4 f1 = *(const float4*)(src + 4);
        uint4 uh, ul;
        split8(f0, f1, uh, ul);
        *(uint4*)&g_Bhi[i8] = uh;
        *(uint4*)&g_Blo[i8] = ul;
    } else {
        const int idx  = blockIdx.x - 512;          // 0..4095
        const int gblk = idx & 127;                 // 128 g-blocks
        const int b    = idx >> 7;                  // 32 batches
        const int warp = threadIdx.x >> 5, lane = threadIdx.x & 31;
        const int g = gblk * 8 + warp;
        const float* wrow = W + (size_t)g * W2;
        const float* h = hidden + (size_t)b * HH;
        float s = 0.f;
        #pragma unroll 8
        for (int k = lane; k < HH; k += 32)
            s += wrow[k] * h[k];
        #pragma unroll
        for (int off = 16; off; off >>= 1)
            s += __shfl_xor_sync(0xffffffffu, s, off);
        if (lane == 0) g_q[b * HH + g] = s + bias[g];
    }
}

// ---------------------------------------------------------------------------
// Main kernel: split-bf16 mma.sync GEMM (BM=128 t, BN=128 g, BK=32).
// 256 threads = 8 warps (4x2), warp tile 32x64, 2 CTAs/SM.
// 3-stage cp.async pipeline, ONE __syncthreads per k-chunk.
// SMEM: unpadded 64B rows, SW64 XOR swizzle (chunk ^= (row>>1)&3).
// A read fp32 from enc, split to bf16 hi/lo in-kernel. grid = (8, 8, 32).
// (R10 exact — proven 652us configuration.)
// ---------------------------------------------------------------------------
#define OFFA_HI 0
#define OFFA_LO 8192
#define OFFB_HI 16384
#define OFFB_LO 24576
#define LO_DELTA 8192
#define STAGE_BYTES 32768
#define SMEM_BYTES (3 * STAGE_BYTES)    // 98304

__global__ void __launch_bounds__(256, 2) energy_kernel(
    const float* __restrict__ enc, const float* __restrict__ v)
{
    extern __shared__ char smem[];
    const uint32_t sb = smem_to_u32(smem);
    __shared__ float esm[128];

    const int tid = threadIdx.x;
    const int lane = tid & 31, wid = tid >> 5;
    const int warp_m = wid & 3, warp_n = wid >> 2;
    const int t0 = blockIdx.x * 128, g0 = blockIdx.y * 128, b = blockIdx.z;

    if (tid < 128) esm[tid] = 0.f;

    // Loader mapping: 2 threads per row; each covers 16 elems (cols half*16..)
    const int lrow = tid >> 1;
    const int half = tid & 1;
    const float* pA = enc + ((size_t)(b * TT + t0 + lrow)) * HH + half * 16;
    const __nv_bfloat16* pBh = g_Bhi + ((size_t)(g0 + lrow)) * HH + half * 16;
    const __nv_bfloat16* pBl = g_Blo + ((size_t)(g0 + lrow)) * HH + half * 16;
    // SW64 swizzled destination offsets (two 16B chunks per thread)
    const uint32_t xr_l = ((uint32_t)lrow >> 1) & 3;
    const uint32_t dstc0 = (uint32_t)lrow * 64 + (((uint32_t)(half * 2 + 0) ^ xr_l) * 16);
    const uint32_t dstc1 = (uint32_t)lrow * 64 + (((uint32_t)(half * 2 + 1) ^ xr_l) * 16);

    float acc[2][8][4];
    #pragma unroll
    for (int i = 0; i < 2; i++)
        #pragma unroll
        for (int j = 0; j < 8; j++)
            #pragma unroll
            for (int k = 0; k < 4; k++) acc[i][j][k] = 0.f;

    // Precomputed ldmatrix offsets (relative to stage base), SW64-swizzled.
    const uint32_t lr15 = (uint32_t)(lane & 15);
    const uint32_t ch   = (uint32_t)(lane >> 4);
    const uint32_t xr   = (lr15 >> 1) & 3;
    uint32_t aoff[2][2], boff[4][2];
    #pragma unroll
    for (int i = 0; i < 2; i++)
        #pragma unroll
        for (int s = 0; s < 2; s++)
            aoff[i][s] = OFFA_HI + (uint32_t)(warp_m * 32 + i * 16 + lr15) * 64
                       + ((((uint32_t)s * 2 + ch) ^ xr) * 16);
    #pragma unroll
    for (int i = 0; i < 4; i++)
        #pragma unroll
        for (int s = 0; s < 2; s++)
            boff[i][s] = OFFB_HI + (uint32_t)(warp_n * 64 + i * 16 + lr15) * 64
                       + ((((uint32_t)s * 2 + ch) ^ xr) * 16);

    #define ISSUE_B(stagebase, kc) do { \
        const int ko_ = (kc) * 32; \
        CP_ASYNC_16((stagebase) + OFFB_HI + dstc0, pBh + ko_); \
        CP_ASYNC_16((stagebase) + OFFB_HI + dstc1, pBh + ko_ + 8); \
        CP_ASYNC_16((stagebase) + OFFB_LO + dstc0, pBl + ko_); \
        CP_ASYNC_16((stagebase) + OFFB_LO + dstc1, pBl + ko_ + 8); \
    } while (0)

    #define STS_A(stageoff, f0, f1, f2, f3) do { \
        uint4 uh, ul; \
        split8(f0, f1, uh, ul); \
        *(uint4*)(smem + (stageoff) + OFFA_HI + dstc0) = uh; \
        *(uint4*)(smem + (stageoff) + OFFA_LO + dstc0) = ul; \
        split8(f2, f3, uh, ul); \
        *(uint4*)(smem + (stageoff) + OFFA_HI + dstc1) = uh; \
        *(uint4*)(smem + (stageoff) + OFFA_LO + dstc1) = ul; \
    } while (0)

    // ---- prologue: fill stages 0 and 1 ----
    #pragma unroll
    for (int st = 0; st < 2; st++) {
        const float* p = pA + st * 32;
        float4 a0 = *(const float4*)(p + 0);
        float4 a1 = *(const float4*)(p + 4);
        float4 a2 = *(const float4*)(p + 8);
        float4 a3 = *(const float4*)(p + 12);
        ISSUE_B(sb + st * STAGE_BYTES, st);
        CP_COMMIT();
        STS_A(st * STAGE_BYTES, a0, a1, a2, a3);
    }

    for (int kc = 0; kc < 32; kc++) {
        const int bufc = kc % 3;
        const int bufn = (kc + 2) % 3;

        float4 a0, a1, a2, a3;
        if (kc < 30) {
            const float* p = pA + (kc + 2) * 32;
            a0 = *(const float4*)(p + 0);
            a1 = *(const float4*)(p + 4);
            a2 = *(const float4*)(p + 8);
            a3 = *(const float4*)(p + 12);
        }

        if (kc == 31) { CP_WAIT(0); } else { CP_WAIT(1); }
        __syncthreads();

        if (kc < 30) {
            ISSUE_B(sb + bufn * STAGE_BYTES, kc + 2);
            CP_COMMIT();
        }

        const uint32_t st = sb + (uint32_t)bufc * STAGE_BYTES;

        // ---- s = 0 ----
        {
            uint32_t ah[2][4], al[2][4];
            #pragma unroll
            for (int mt = 0; mt < 2; mt++) {
                LDSM4(ah[mt], st + aoff[mt][0]);
                LDSM4(al[mt], st + aoff[mt][0] + LO_DELTA);
            }
            #pragma unroll
            for (int np = 0; np < 4; np++) {
                uint32_t bh[4], bl[4];
                LDSM4(bh, st + boff[np][0]);
                LDSM4(bl, st + boff[np][0] + LO_DELTA);
                float* a00 = acc[0][np * 2 + 0];
                float* a01 = acc[0][np * 2 + 1];
                float* a10 = acc[1][np * 2 + 0];
                float* a11 = acc[1][np * 2 + 1];
                MMA16816(a00, ah[0], bh[0], bh[2]);
                MMA16816(a10, ah[1], bh[0], bh[2]);
                MMA16816(a01, ah[0], bh[1], bh[3]);
                MMA16816(a11, ah[1], bh[1], bh[3]);
                MMA16816(a00, ah[0], bl[0], bl[2]);
                MMA16816(a10, ah[1], bl[0], bl[2]);
                MMA16816(a01, ah[0], bl[1], bl[3]);
                MMA16816(a11, ah[1], bl[1], bl[3]);
                MMA16816(a00, al[0], bh[0], bh[2]);
                MMA16816(a10, al[1], bh[0], bh[2]);
                MMA16816(a01, al[0], bh[1], bh[3]);
                MMA16816(a11, al[1], bh[1], bh[3]);
            }
        }

        // split + store A for stage kc+2 (buffer freed by this iter's sync)
        if (kc < 30)
            STS_A((uint32_t)bufn * STAGE_BYTES, a0, a1, a2, a3);

        // ---- s = 1 ----
        {
            uint32_t ah[2][4], al[2][4];
            #pragma unroll
            for (int mt = 0; mt < 2; mt++) {
                LDSM4(ah[mt], st + aoff[mt][1]);
                LDSM4(al[mt], st + aoff[mt][1] + LO_DELTA);
            }
            #pragma unroll
            for (int np = 0; np < 4; np++) {
                uint32_t bh[4], bl[4];
                LDSM4(bh, st + boff[np][1]);
                LDSM4(bl, st + boff[np][1] + LO_DELTA);
                float* a00 = acc[0][np * 2 + 0];
                float* a01 = acc[0][np * 2 + 1];
                float* a10 = acc[1][np * 2 + 0];
                float* a11 = acc[1][np * 2 + 1];
                MMA16816(a00, ah[0], bh[0], bh[2]);
                MMA16816(a10, ah[1], bh[0], bh[2]);
                MMA16816(a01, ah[0], bh[1], bh[3]);
                MMA16816(a11, ah[1], bh[1], bh[3]);
                MMA16816(a00, ah[0], bl[0], bl[2]);
                MMA16816(a10, ah[1], bl[0], bl[2]);
                MMA16816(a01, ah[0], bl[1], bl[3]);
                MMA16816(a11, ah[1], bl[1], bl[3]);
                MMA16816(a00, al[0], bh[0], bh[2]);
                MMA16816(a10, al[1], bh[0], bh[2]);
                MMA16816(a01, al[0], bh[1], bh[3]);
                MMA16816(a11, al[1], bh[1], bh[3]);
            }
        }
    }

    // ---- epilogue: tanh(acc + q) * v, reduce per t-row ----
    const float* qrow = g_q + b * HH + g0 + warp_n * 64;
    const float* vrow = v + g0 + warp_n * 64;
    float part[2][2] = {{0.f, 0.f}, {0.f, 0.f}};
    #pragma unroll
    for (int np = 0; np < 4; np++) {
        #pragma unroll
        for (int nt = 0; nt < 2; nt++) {
            const int gl = np * 16 + nt * 8 + (lane & 3) * 2;
            const float2 q2 = *(const float2*)(qrow + gl);
            const float2 v2 = *(const float2*)(vrow + gl);
            #pragma unroll
            for (int mt = 0; mt < 2; mt++) {
                const float* c = acc[mt][np * 2 + nt];
                #pragma unroll
                for (int rh = 0; rh < 2; rh++) {
                    part[mt][rh] += fast_tanh(c[rh * 2 + 0] + q2.x) * v2.x
                                  + fast_tanh(c[rh * 2 + 1] + q2.y) * v2.y;
                }
            }
        }
    }
    #pragma unroll
    for (int mt = 0; mt < 2; mt++) {
        #pragma unroll
        for (int rh = 0; rh < 2; rh++) {
            float p = part[mt][rh];
            p += __shfl_xor_sync(0xffffffffu, p, 1);
            p += __shfl_xor_sync(0xffffffffu, p, 2);
            if ((lane & 3) == 0)
                atomicAdd(&esm[warp_m * 32 + mt * 16 + rh * 8 + (lane >> 2)], p);
        }
    }
    __syncthreads();
    if (tid < 128)
        g_epart[blockIdx.y][b][t0 + tid] = esm[tid];
}

// ---------------------------------------------------------------------------
// Softmax over t: 1024 threads, one element per thread (two-level reduce).
// ---------------------------------------------------------------------------
__global__ void __launch_bounds__(1024) softmax_kernel(float* __restrict__ out)
{
    const int b = blockIdx.x;
    const int tid = threadIdx.x;
    const int lane = tid & 31, wid = tid >> 5;
    __shared__ float red[32];
    __shared__ float bc;

    float e = 0.f;
    #pragma unroll
    for (int sl = 0; sl < 8; sl++) e += g_epart[sl][b][tid];

    float m = e;
    #pragma unroll
    for (int off = 16; off; off >>= 1) m = fmaxf(m, __shfl_xor_sync(0xffffffffu, m, off));
    if (lane == 0) red[wid] = m;
    __syncthreads();
    if (tid < 32) {
        float mm = red[tid];
        #pragma unroll
        for (int off = 16; off; off >>= 1) mm = fmaxf(mm, __shfl_xor_sync(0xffffffffu, mm, off));
        if (tid == 0) bc = mm;
    }
    __syncthreads();
    const float M = bc;

    float ex = expf(e - M);
    float s = ex;
    #pragma unroll
    for (int off = 16; off; off >>= 1) s += __shfl_xor_sync(0xffffffffu, s, off);
    if (lane == 0) red[wid] = s;
    __syncthreads();
    if (tid < 32) {
        float ss = red[tid];
        #pragma unroll
        for (int off = 16; off; off >>= 1) ss += __shfl_xor_sync(0xffffffffu, ss, off);
        if (tid == 0) bc = 1.0f / ss;
    }
    __syncthreads();

    out[(size_t)b * TT + tid] = ex * bc;
}

// ---------------------------------------------------------------------------
extern "C" void kernel_launch(void* const* d_in, const int* in_sizes, int n_in,
                              void* d_out, int out_size)
{
    const float* hidden = (const float*)d_in[0];  // (1, 32, 1024)
    const float* enc    = (const float*)d_in[1];  // (32, 1024, 1024)
    const float* W      = (const float*)d_in[2];  // (1024, 2048)
    const float* bias   = (const float*)d_in[3];  // (1024,)
    const float* v      = (const float*)d_in[4];  // (1024,)
    float* out = (float*)d_out;                   // (32, 1, 1024)

    cudaFuncSetAttribute(energy_kernel,
                         cudaFuncAttributeMaxDynamicSharedMemorySize, SMEM_BYTES);

    prep_kernel<<<512 + 4096, 256>>>(W, hidden, bias);
    energy_kernel<<<dim3(TT / 128, HH / 128, BB), 256, SMEM_BYTES>>>(enc, v);
    softmax_kernel<<<BB, 1024>>>(out);
}